// round 15
// baseline (speedup 1.0000x reference)
#include <cuda_runtime.h>
#include <cuda_bf16.h>
#include <cstdint>

// image_output: [8, 512, 512, 32] f32; slic: [8,512,512,1] i32 in [0,256]
// out[s][b][c] = sum(img where slic-1==s) / count(nonzero img where slic-1==s)

#define BATCH 8
#define HW (512 * 512)
#define CH 32
#define NSEG 256
#define DROW NSEG
#define ROWS (NSEG + 1)

#define CW 3                                // consumer warps (SMSPs 0-2)
#define NTHREADS 128                        // + counting warp on SMSP 3
#define BPB 37                              // 296 blocks = one wave @2/SM
#define GRID_ACC (BATCH * BPB)
#define CHUNK ((HW + BPB - 1) / BPB)        // 7086
#define RPX (CW * 32)                       // 96 px per block round

#define ACCF (ROWS * CH)                    // 8224 floats per consumer-warp acc
#define SMEM_BYTES (CW * ACCF * 4)          // 98688 dyn -> 2 blocks/SM

#define PARTF (NSEG * CH + NSEG)            // per-block partial: sums + counts

__device__ float g_part[GRID_ACC][PARTF];
__device__ float g_zc[BATCH][NSEG][CH];     // exact-zero corrections.
// INVARIANT: g_zc == 0 at every kernel_launch entry (finalize re-zeros).

// ---------------------------------------------------------------------------
// One round = 16 steps x 2 px = 32 px. Lane (h,q) handles channels (2q,2q+1)
// of pixel 2u+h via float2. Word (row, 2q) is written by lanes (0,q),(1,q),
// so the fast path requires no duplicate rows at pixel distance 1..7.
// (Byte-identical to the R14-validated version.)
// ---------------------------------------------------------------------------
__device__ __forceinline__ void process32(
    const float2 v[16], int rowv, float* __restrict__ acc,
    int lane, int h, int q, bool& zacc)
{
    const unsigned FULL = 0xffffffffu;

    bool bad = false;
    #pragma unroll
    for (int d = 1; d <= 7; ++d) {
        int rd = __shfl_up_sync(FULL, rowv, d);
        bad |= (lane >= d) && (rowv == rd);
    }
    unsigned badm = __ballot_sync(FULL, bad);

    float mn = fminf(fabsf(v[0].x), fabsf(v[0].y));
    #pragma unroll
    for (int u = 1; u < 16; ++u)
        mn = fminf(mn, fminf(fabsf(v[u].x), fabsf(v[u].y)));
    zacc |= (mn == 0.0f);

    if (badm == 0) {
        // FAST (~42%): all rows distinct within distance 7 -> no same-step
        // dup, no aliasing with prefetch-3, no serial dependency.
        int er[16];
        #pragma unroll
        for (int u = 0; u < 16; ++u) er[u] = __shfl_sync(FULL, rowv, 2 * u + h);
        float2 p0 = *(float2*)(acc + er[0] * CH + 2 * q);
        float2 p1 = *(float2*)(acc + er[1] * CH + 2 * q);
        float2 p2 = *(float2*)(acc + er[2] * CH + 2 * q);
        #pragma unroll
        for (int u = 0; u < 16; ++u) {
            float2 a; a.x = p0.x + v[u].x; a.y = p0.y + v[u].y;
            float2 np = make_float2(0.f, 0.f);
            if (u + 3 < 16) np = *(float2*)(acc + er[u + 3] * CH + 2 * q);
            *(float2*)(acc + er[u] * CH + 2 * q) = a;
            p0 = p1; p1 = p2; p2 = np;
        }
    } else {
        // SLOW: per-step intra-pair dedup (absorber h==0 takes both values,
        // h==1 redirects to dummy row), then strictly serial float2 RMW --
        // exact by warp program order across steps.
        int dup = (rowv == __shfl_xor_sync(FULL, rowv, 1)) ? 1 : 0;
        int pk  = (rowv << 1) | dup;
        #pragma unroll
        for (int u = 0; u < 16; ++u) {
            int   m  = __shfl_sync(FULL, pk, 2 * u + h);
            float px = __shfl_xor_sync(FULL, v[u].x, 16);
            float py = __shfl_xor_sync(FULL, v[u].y, 16);
            int   er = m >> 1;
            bool  d  = (m & 1) != 0;
            float ax = v[u].x + ((d && h == 0) ? px : 0.0f);
            float ay = v[u].y + ((d && h == 0) ? py : 0.0f);
            int   e  = (d && h == 1) ? DROW : er;
            float2* w = (float2*)(acc + e * CH + 2 * q);
            float2 cur = *w;
            cur.x += ax; cur.y += ay;
            *w = cur;
        }
    }
}

// ---------------------------------------------------------------------------
// Kernel A: fused segmented accumulation + counting.
// Warps 0-2 (SMSPs 0-2): float2 sums, depth-4 register ring.
// Warp 3   (SMSP 3, otherwise idle): per-segment pixel counts for the chunk.
// ---------------------------------------------------------------------------
#define LOAD_ROUND(BUF, RV, k) do {                                          \
    int pb_ = start + (int)(k) * RPX + warp * 32;                            \
    pb_ = (pb_ > end - 32) ? (end - 32) : pb_;   /* clamp: always in range */\
    const float2* ip_ = (const float2*)imgb + (size_t)(pb_ + h) * 16 + q;    \
    _Pragma("unroll")                                                        \
    for (int u_ = 0; u_ < 16; ++u_) BUF[u_] = __ldcs(ip_ + u_ * 32);         \
    int sv_ = slicb[pb_ + lane];                                             \
    RV = (sv_ == 0) ? DROW : (sv_ - 1);                                      \
} while (0)

__global__ void __launch_bounds__(NTHREADS, 2)
accum_kernel(const float* __restrict__ img, const int* __restrict__ slic) {
    extern __shared__ float smem[];
    __shared__ int zflag[CW];
    __shared__ int cnt[NSEG];
    const int tid  = threadIdx.x;
    const int warp = tid >> 5;
    const int lane = tid & 31;
    const int h    = lane >> 4;
    const int q    = lane & 15;
    if (warp < CW && lane == 0) zflag[warp] = 0;

    for (int i = tid; i < CW * ACCF / 4; i += NTHREADS)
        ((float4*)smem)[i] = make_float4(0.f, 0.f, 0.f, 0.f);
    __syncthreads();

    const int batch = blockIdx.x / BPB;
    const int blk   = blockIdx.x % BPB;
    const float* imgb  = img  + (size_t)batch * HW * CH;
    const int*   slicb = slic + (size_t)batch * HW;

    const int start = blk * CHUNK;
    int end = start + CHUNK; if (end > HW) end = HW;
    const int n = end - start;
    const int nfull = n / RPX;                  // 96-px block rounds (~73)

    const unsigned FULL = 0xffffffffu;

    if (warp == 3) {
        // ---- Counting warp: per-segment pixel counts for [start, end). ----
        for (int i = lane; i < NSEG; i += 32) cnt[i] = 0;
        __syncwarp();
        int p = start + lane;
        for (; p + 96 < end; p += 128) {
            int s0 = slicb[p];
            int s1 = slicb[p + 32];
            int s2 = slicb[p + 64];
            int s3 = slicb[p + 96];
            if (s0) atomicAdd(&cnt[s0 - 1], 1);
            if (s1) atomicAdd(&cnt[s1 - 1], 1);
            if (s2) atomicAdd(&cnt[s2 - 1], 1);
            if (s3) atomicAdd(&cnt[s3 - 1], 1);
        }
        for (; p < end; p += 32) {
            int s = slicb[p];
            if (s) atomicAdd(&cnt[s - 1], 1);
        }
    } else {
        // ---- Consumer warps 0-2: depth-4 float2 register ring. ----
        float* acc = smem + warp * ACCF;
        bool zacc = false;

        float2 B0[16], B1[16], B2[16], B3[16];
        int    S0, S1, S2, S3;
        LOAD_ROUND(B0, S0, 0);
        LOAD_ROUND(B1, S1, 1);
        LOAD_ROUND(B2, S2, 2);

        int r = 0;
        for (; r + 4 <= nfull; r += 4) {
            LOAD_ROUND(B3, S3, r + 3); process32(B0, S0, acc, lane, h, q, zacc);
            LOAD_ROUND(B0, S0, r + 4); process32(B1, S1, acc, lane, h, q, zacc);
            LOAD_ROUND(B1, S1, r + 5); process32(B2, S2, acc, lane, h, q, zacc);
            LOAD_ROUND(B2, S2, r + 6); process32(B3, S3, acc, lane, h, q, zacc);
        }
        const int rem = nfull - r;
        if (rem > 0) process32(B0, S0, acc, lane, h, q, zacc);
        if (rem > 1) process32(B1, S1, acc, lane, h, q, zacc);
        if (rem > 2) process32(B2, S2, acc, lane, h, q, zacc);

        // Tail: < 96 leftover pixels; h==0 lanes own distinct float2 words.
        for (int p = start + nfull * RPX + warp; p < end; p += CW) {
            int s = slicb[p];
            int rw = (s == 0) ? DROW : (s - 1);
            if (h == 0) {
                float2 x = *((const float2*)imgb + (size_t)p * 16 + q);
                float2* w = (float2*)(acc + rw * CH + 2 * q);
                float2 cur = *w;
                cur.x += x.x; cur.y += x.y;
                *w = cur;
                zacc |= (x.x == 0.0f) | (x.y == 0.0f);
            }
        }

        if (__ballot_sync(FULL, zacc) && lane == 0) zflag[warp] = 1;
    }

    // Merge 3 consumer accumulators + counts -> g_part[blk].
    __syncthreads();
    float* outp = g_part[blockIdx.x];
    #pragma unroll 4
    for (int i = tid; i < NSEG * CH / 4; i += NTHREADS) {
        float4 a = ((const float4*)smem)[i];
        #pragma unroll
        for (int w = 1; w < CW; ++w) {
            float4 b = ((const float4*)(smem + w * ACCF))[i];
            a.x += b.x; a.y += b.y; a.z += b.z; a.w += b.w;
        }
        ((float4*)outp)[i] = a;
    }
    for (int i = tid; i < NSEG; i += NTHREADS)
        outp[NSEG * CH + i] = (float)cnt[i];

    // Exact-zero correction path (essentially never taken; exact when it is).
    int anyz = zflag[0] | zflag[1] | zflag[2];
    if (anyz && warp < CW) {
        for (int p = start + warp; p < end; p += CW) {
            int s = slicb[p];
            if (s == 0) continue;
            float x = imgb[(size_t)p * CH + lane];
            if (x == 0.0f) atomicAdd(&g_zc[batch][s - 1][lane], 1.0f);
        }
    }
}

// ---------------------------------------------------------------------------
// Kernel B: 4-way k-split reduction (sums + counts from g_part) + divide.
// ---------------------------------------------------------------------------
__global__ void finalize_kernel(float* __restrict__ out) {
    __shared__ float ssum[256], scnt[256];
    const int t = threadIdx.x;
    const int slice = t >> 6;                          // 0..3
    const int o = (blockIdx.x << 6) | (t & 63);        // output id 0..65535
    const int c = o & (CH - 1);
    const int s = (o >> 5) & (NSEG - 1);
    const int b = o >> 13;

    float sum = 0.0f, cn = 0.0f;
    {
        int k0 = (slice * BPB) >> 2, k1 = ((slice + 1) * BPB) >> 2;
        int pb = b * BPB;
        for (int k = k0; k < k1; ++k) {
            sum += g_part[pb + k][s * CH + c];         // coalesced over c
            cn  += g_part[pb + k][NSEG * CH + s];      // warp-broadcast
        }
    }
    ssum[t] = sum; scnt[t] = cn;
    __syncthreads();

    if (t < 64) {
        sum = ssum[t] + ssum[t + 64] + ssum[t + 128] + ssum[t + 192];
        cn  = scnt[t] + scnt[t + 64] + scnt[t + 128] + scnt[t + 192];
        cn -= g_zc[b][s][c];
        g_zc[b][s][c] = 0.0f;                          // restore invariant
        out[((size_t)s * BATCH + b) * CH + c] = sum / cn;
    }
}

// ---------------------------------------------------------------------------
extern "C" void kernel_launch(void* const* d_in, const int* in_sizes, int n_in,
                              void* d_out, int out_size) {
    const float* img  = (const float*)d_in[0];
    const int*   slic = (const int*)d_in[1];
    float* out = (float*)d_out;

    // accum first so ncu's bounded capture profiles the hot kernel.
    cudaFuncSetAttribute(accum_kernel,
                         cudaFuncAttributeMaxDynamicSharedMemorySize, SMEM_BYTES);
    accum_kernel<<<GRID_ACC, NTHREADS, SMEM_BYTES>>>(img, slic);

    finalize_kernel<<<1024, 256>>>(out);
}